// round 15
// baseline (speedup 1.0000x reference)
#include <cuda_runtime.h>
#include <math.h>

#define TSEQ   1024
#define NSTEP  (TSEQ + 1)
#define NBATCH 64
#define HID    512
#define G3     1536
#define INFEAT 256
#define MROWS  (TSEQ * NBATCH)   // 65536
#define NCTA   128
#define NTH    384
#define SL     (32 * 26)         // one warp-slice of the reduction buffer

// packed f32x2 FMA
#define FMA2(d, a, b, c) \
    asm("fma.rn.f32x2 %0, %1, %2, %3;" : "=l"(d) : "l"(a), "l"(b), "l"(c))

__device__ __forceinline__ float2 u2f2(unsigned long long u) {
    float2 f;
    asm("mov.b64 {%0, %1}, %2;" : "=f"(f.x), "=f"(f.y) : "l"(u));
    return f;
}

// ---------------- scratch (device globals; no allocation) ----------------
__device__ float g_xg[(size_t)MROWS * G3];    // layer0 gate preacts (proj0)
__device__ float g_h0[3][HID * NBATCH];       // layer0 h ring (k-major); [2]=zero
__device__ float g_h1[3][HID * NBATCH];       // layer1 h ring; [2]=zero
__device__ float g_y0r[2][HID * NBATCH];      // y0 ring (k-major)
__device__ unsigned g_cntB[2 * 32];           // per-bgrp barrier count (ret 0)
__device__ unsigned g_genB[2 * 32];           // per-bgrp generation (monotonic)

// ---------------- input projection GEMM (layer 0 only) ----------------
__global__ void __launch_bounds__(256) proj_kernel(
    const float* __restrict__ A, const float* __restrict__ W,
    const float* __restrict__ bias, int K, long sB, long sT)
{
    const int N = G3;
    __shared__ __align__(16) float As2[16][260];
    __shared__ __align__(16) float Bs[16][64];

    int tid  = threadIdx.x;
    int row0 = blockIdx.y * 128;
    int col0 = blockIdx.x * 64;
    int tx = tid & 15, ty = tid >> 4;

    int ar  = row0 + (tid >> 1);
    const float* arow = A + (long)(ar & 63) * sB + (long)(ar >> 6) * sT;
    int akc = (tid & 1) * 8;
    int r2  = (tid >> 1) * 2;

    int bkr = tid >> 4;
    int bc  = (tid & 15) * 4;
    const float* bptr = W + (long)bkr * N + col0 + bc;

    unsigned long long acc[8][2];
#pragma unroll
    for (int i = 0; i < 8; ++i) { acc[i][0] = 0ull; acc[i][1] = 0ull; }

    for (int k0 = 0; k0 < K; k0 += 16) {
        float4 a0 = *(const float4*)(arow + k0 + akc);
        float4 a1 = *(const float4*)(arow + k0 + akc + 4);
        float4 bb = *(const float4*)(bptr + (long)k0 * N);

        *(float2*)&As2[akc + 0][r2] = make_float2(a0.x, a0.x);
        *(float2*)&As2[akc + 1][r2] = make_float2(a0.y, a0.y);
        *(float2*)&As2[akc + 2][r2] = make_float2(a0.z, a0.z);
        *(float2*)&As2[akc + 3][r2] = make_float2(a0.w, a0.w);
        *(float2*)&As2[akc + 4][r2] = make_float2(a1.x, a1.x);
        *(float2*)&As2[akc + 5][r2] = make_float2(a1.y, a1.y);
        *(float2*)&As2[akc + 6][r2] = make_float2(a1.z, a1.z);
        *(float2*)&As2[akc + 7][r2] = make_float2(a1.w, a1.w);
        *(float4*)&Bs[bkr][bc] = bb;
        __syncthreads();

#pragma unroll
        for (int kk = 0; kk < 16; ++kk) {
            ulonglong2 b01 = *(const ulonglong2*)&Bs[kk][tx * 4];
            ulonglong2 a01 = *(const ulonglong2*)&As2[kk][ty * 16];
            ulonglong2 a23 = *(const ulonglong2*)&As2[kk][ty * 16 + 4];
            ulonglong2 a45 = *(const ulonglong2*)&As2[kk][ty * 16 + 8];
            ulonglong2 a67 = *(const ulonglong2*)&As2[kk][ty * 16 + 12];
            unsigned long long ad[8] = {a01.x, a01.y, a23.x, a23.y,
                                        a45.x, a45.y, a67.x, a67.y};
#pragma unroll
            for (int i = 0; i < 8; ++i) {
                FMA2(acc[i][0], ad[i], b01.x, acc[i][0]);
                FMA2(acc[i][1], ad[i], b01.y, acc[i][1]);
            }
        }
        __syncthreads();
    }

    float4 bia = *(const float4*)(bias + col0 + tx * 4);
#pragma unroll
    for (int i = 0; i < 8; ++i) {
        long m = row0 + ty * 8 + i;
        float2 f01 = u2f2(acc[i][0]);
        float2 f23 = u2f2(acc[i][1]);
        float4 v;
        v.x = f01.x + bia.x;
        v.y = f01.y + bia.y;
        v.z = f23.x + bia.z;
        v.w = f23.y + bia.w;
        *(float4*)(g_xg + m * G3 + col0 + tx * 4) = v;
    }
}

// ---------------- per-task GEMM body (one warp: 128 k, 24 gate cols) -------
// src: k-major [512][64] global; wsl: SMEM [512][24]; redsl: [4][32][26]
__device__ __forceinline__ void task_gemm(
    const float* __restrict__ src, const float* __restrict__ wsl,
    float* __restrict__ redsl, int wt, int lane, int b0)
{
    unsigned long long acc[12];
#pragma unroll
    for (int j = 0; j < 12; ++j) acc[j] = 0ull;
    int kbase = wt << 7;                      // 128 k per warp
    const float* hp = src + kbase * NBATCH + b0 + lane;
    const ulonglong2* wp = (const ulonglong2*)(wsl + kbase * 24);
#pragma unroll 8
    for (int kk = 0; kk < 128; ++kk) {
        float hv = __ldcg(hp); hp += NBATCH;
        unsigned long long hd;
        asm("mov.b64 %0, {%1, %1};" : "=l"(hd) : "r"(__float_as_int(hv)));
        ulonglong2 w0 = wp[0], w1 = wp[1], w2 = wp[2];
        FMA2(acc[0],  hd, w0.x, acc[0]);
        FMA2(acc[1],  hd, w0.y, acc[1]);
        FMA2(acc[2],  hd, w1.x, acc[2]);
        FMA2(acc[3],  hd, w1.y, acc[3]);
        FMA2(acc[4],  hd, w2.x, acc[4]);
        FMA2(acc[5],  hd, w2.y, acc[5]);
        ulonglong2 w3 = wp[3], w4 = wp[4], w5 = wp[5];
        FMA2(acc[6],  hd, w3.x, acc[6]);
        FMA2(acc[7],  hd, w3.y, acc[7]);
        FMA2(acc[8],  hd, w4.x, acc[8]);
        FMA2(acc[9],  hd, w4.y, acc[9]);
        FMA2(acc[10], hd, w5.x, acc[10]);
        FMA2(acc[11], hd, w5.y, acc[11]);
        wp += 6;   // row stride = 24 floats = 6 ulonglong2
    }
    unsigned long long* rp =
        (unsigned long long*)(redsl + (wt * 32 + lane) * 26);
#pragma unroll
    for (int j = 0; j < 12; ++j) rp[j] = acc[j];
}

// ---------------- fused persistent pipeline (TX merged into T1) ------------
// 128 CTAs x 384 threads. CTA (bgrp, colgrp): batch [bgrp*32,+32), hidden
// cols [colgrp*8,+8). Step s: warps 0-3 T0 GEMM (t0=s), warps 4-7 T1 h-side
// (h1(t1-1)@Wh1), warps 8-11 T1 y-side (y0(t1)@Wi1), t1=s-1. The y-side and
// h-side reductions stay separate in SMEM, so the n-gate gets xn/hn split
// without any global xg1 ring. Pipeline depth 1.
__global__ void __launch_bounds__(NTH, 1) gru_fused_kernel(
    const float* __restrict__ Wh0, const float* __restrict__ bhn0,
    const float* __restrict__ Wi1, const float* __restrict__ bi1,
    const float* __restrict__ Wh1, const float* __restrict__ bhn1,
    float* __restrict__ c0out, float* __restrict__ c1out)
{
    const int NG = 24;
    extern __shared__ __align__(16) float sh[];
    float* ws0 = sh;                  // [512][24] W_h0 slice
    float* wsi = ws0 + 512 * NG;      // [512][24] W_i1 slice
    float* ws1 = wsi + 512 * NG;      // [512][24] W_h1 slice
    float* red = ws1 + 512 * NG;      // [12][32][26]: 0-3 T0, 4-7 T1h, 8-11 T1y
    float* xgs = red + 12 * SL;       // [32][25]

    int tid  = threadIdx.x;
    int warp = tid >> 5, lane = tid & 31;
    int cta  = blockIdx.x;
    int bgrp = cta & 1;
    int hc0  = (cta >> 1) * 8;
    int b0   = bgrp * 32;

    unsigned* cntp = &g_cntB[bgrp * 32];
    unsigned* genp = &g_genB[bgrp * 32];

    // load the three weight slices (once); gate col gc for slice col j
    for (int f = tid; f < 512 * NG; f += NTH) {
        int k = f / NG, j = f - k * NG;
        int gc = (j >> 3) * HID + hc0 + (j & 7);
        ws0[f] = Wh0[(long)k * G3 + gc];
        wsi[f] = Wi1[(long)k * G3 + gc];
        ws1[f] = Wh1[(long)k * G3 + gc];
    }

    unsigned base = *((volatile unsigned*)genp);

    // gate-phase mapping: group gt of 128 threads; gt0 -> T0, gt1 -> T1
    int gt  = tid >> 7;               // 0,1,2 (group 2 idle in gate phase)
    int gi  = tid & 127;
    int eb  = gi & 31;
    int ec0 = gi >> 5;                // 0..3
    int ec1 = ec0 + 4;                // 4..7
    int ehc0 = hc0 + ec0, ehc1 = hc0 + ec1;

    // per-group gate constants
    float cA0 = 0.f, cA1 = 0.f;                       // bhn (layer 0 or 1)
    float br0 = 0.f, br1 = 0.f, bz0 = 0.f, bz1 = 0.f, bn0 = 0.f, bn1 = 0.f;
    if (gt == 0) { cA0 = bhn0[ehc0]; cA1 = bhn0[ehc1]; }
    if (gt == 1) {
        cA0 = bhn1[ehc0];        cA1 = bhn1[ehc1];
        br0 = bi1[ehc0];         br1 = bi1[ehc1];
        bz0 = bi1[512 + ehc0];   bz1 = bi1[512 + ehc1];
        bn0 = bi1[1024 + ehc0];  bn1 = bi1[1024 + ehc1];
    }

    // xg0 prefetch registers (warps 0-2: gate group = warp, b = lane)
    float4 xv0, xv1;
    const float* xg_base = 0;
    if (tid < 96) {
        int b = tid & 31, gg = tid >> 5;
        xg_base = g_xg + (long)(b0 + b) * G3 + gg * HID + hc0;
        xv0 = ((const float4*)xg_base)[0];   // t0 = 0
        xv1 = ((const float4*)xg_base)[1];
    }

    for (int s = 0; s < NSTEP; ++s) {
        int t1 = s - 1;
        bool doT0 = (s < TSEQ);
        bool doT1 = (s >= 1);

        const float* hbuf0 = (s == 0) ? g_h0[2] : g_h0[s & 1];
        const float* hbuf1 = (t1 == 0) ? g_h1[2] : g_h1[t1 & 1];

        // hoisted gate-operand loads (latency hidden under GEMM phase)
        float hp00 = 0.f, hp01 = 0.f, hp10 = 0.f, hp11 = 0.f;
        if (gt == 0 && doT0) {
            hp00 = __ldcg(&hbuf0[ehc0 * NBATCH + b0 + eb]);
            hp01 = __ldcg(&hbuf0[ehc1 * NBATCH + b0 + eb]);
        }
        if (gt == 1 && doT1) {
            hp10 = __ldcg(&hbuf1[ehc0 * NBATCH + b0 + eb]);
            hp11 = __ldcg(&hbuf1[ehc1 * NBATCH + b0 + eb]);
        }

        // stage prefetched xg0 tile (read in gate phase, after the sync)
        if (tid < 96) {
            int b = tid & 31, gg = tid >> 5;
            float* q = xgs + b * 25 + gg * 8;
            q[0] = xv0.x; q[1] = xv0.y; q[2] = xv0.z; q[3] = xv0.w;
            q[4] = xv1.x; q[5] = xv1.y; q[6] = xv1.z; q[7] = xv1.w;
        }

        // ======== GEMM phase: three warp groups, fully concurrent ========
        if (warp < 4)      { if (doT0) task_gemm(hbuf0, ws0, red,          warp,     lane, b0); }
        else if (warp < 8) { if (doT1) task_gemm(hbuf1, ws1, red + 4 * SL, warp - 4, lane, b0); }
        else               { if (doT1) task_gemm(g_y0r[t1 & 1], wsi, red + 8 * SL, warp - 8, lane, b0); }
        __syncthreads();

        // ======== gate phase ========
        if (gt == 0 && doT0) {
            float hr0 = 0.f, hz0 = 0.f, hn0 = 0.f;
            float hr1 = 0.f, hz1 = 0.f, hn1 = 0.f;
#pragma unroll
            for (int w = 0; w < 4; ++w) {
                const float* pr = red + (w * 32 + eb) * 26;
                hr0 += pr[ec0];      hr1 += pr[ec1];
                hz0 += pr[8 + ec0];  hz1 += pr[8 + ec1];
                hn0 += pr[16 + ec0]; hn1 += pr[16 + ec1];
            }
            float xr0 = xgs[eb * 25 + ec0],      xr1v = xgs[eb * 25 + ec1];
            float xz0 = xgs[eb * 25 + 8 + ec0],  xz1v = xgs[eb * 25 + 8 + ec1];
            float xn0 = xgs[eb * 25 + 16 + ec0], xn1v = xgs[eb * 25 + 16 + ec1];

            float rg0 = 1.f / (1.f + __expf(-(xr0 + hr0)));
            float zg0 = 1.f / (1.f + __expf(-(xz0 + hz0)));
            float ng0 = tanhf(xn0 + rg0 * (hn0 + cA0));
            float hnew0 = (1.f - zg0) * ng0 + zg0 * hp00;
            float rg1 = 1.f / (1.f + __expf(-(xr1v + hr1)));
            float zg1 = 1.f / (1.f + __expf(-(xz1v + hz1)));
            float ng1 = tanhf(xn1v + rg1 * (hn1 + cA1));
            float hnew1 = (1.f - zg1) * ng1 + zg1 * hp01;

            int nb = (s & 1) ^ 1;
            g_h0[nb][ehc0 * NBATCH + b0 + eb] = hnew0;
            g_h0[nb][ehc1 * NBATCH + b0 + eb] = hnew1;
            g_y0r[s & 1][ehc0 * NBATCH + b0 + eb] = tanhf(hnew0);
            g_y0r[s & 1][ehc1 * NBATCH + b0 + eb] = tanhf(hnew1);
            if (s == TSEQ - 1) {
                c0out[(b0 + eb) * HID + ehc0] = hnew0;
                c0out[(b0 + eb) * HID + ehc1] = hnew1;
            }
        }

        if (gt == 1 && doT1) {
            // h-side (slices 4-7) and y-side (slices 8-11) kept separate
            float hr0 = 0.f, hz0 = 0.f, hn0 = 0.f;
            float hr1 = 0.f, hz1 = 0.f, hn1 = 0.f;
            float yr0 = 0.f, yz0 = 0.f, yn0 = 0.f;
            float yr1 = 0.f, yz1 = 0.f, yn1 = 0.f;
#pragma unroll
            for (int w = 0; w < 4; ++w) {
                const float* ph = red + 4 * SL + (w * 32 + eb) * 26;
                const float* py = red + 8 * SL + (w * 32 + eb) * 26;
                hr0 += ph[ec0];      hr1 += ph[ec1];
                hz0 += ph[8 + ec0];  hz1 += ph[8 + ec1];
                hn0 += ph[16 + ec0]; hn1 += ph[16 + ec1];
                yr0 += py[ec0];      yr1 += py[ec1];
                yz0 += py[8 + ec0];  yz1 += py[8 + ec1];
                yn0 += py[16 + ec0]; yn1 += py[16 + ec1];
            }
            float xr0 = yr0 + br0, xz0 = yz0 + bz0, xn0 = yn0 + bn0;
            float xr1v = yr1 + br1, xz1v = yz1 + bz1, xn1v = yn1 + bn1;

            float rg0 = 1.f / (1.f + __expf(-(xr0 + hr0)));
            float zg0 = 1.f / (1.f + __expf(-(xz0 + hz0)));
            float ng0 = tanhf(xn0 + rg0 * (hn0 + cA0));
            float hnew0 = (1.f - zg0) * ng0 + zg0 * hp10;
            float rg1 = 1.f / (1.f + __expf(-(xr1v + hr1)));
            float zg1 = 1.f / (1.f + __expf(-(xz1v + hz1)));
            float ng1 = tanhf(xn1v + rg1 * (hn1 + cA1));
            float hnew1 = (1.f - zg1) * ng1 + zg1 * hp11;

            int nb = (t1 & 1) ^ 1;
            g_h1[nb][ehc0 * NBATCH + b0 + eb] = hnew0;
            g_h1[nb][ehc1 * NBATCH + b0 + eb] = hnew1;
            if (t1 == TSEQ - 1) {
                c1out[(b0 + eb) * HID + ehc0] = hnew0;
                c1out[(b0 + eb) * HID + ehc1] = hnew1;
            }
        }

        __syncthreads();   // all CTA writes issued before tid0's release

        unsigned target = base + (unsigned)s + 1u;

        // arrive: per-bgrp flat release-atomic (64 arrivals)
        if (tid == 0) {
            unsigned old;
            asm volatile("atom.release.gpu.global.add.u32 %0, [%1], %2;"
                         : "=r"(old) : "l"(cntp), "r"(1u) : "memory");
            if (old == 63u) {
                asm volatile("st.global.u32 [%0], %1;"
                             :: "l"(cntp), "r"(0u) : "memory");
                asm volatile("st.release.gpu.global.u32 [%0], %1;"
                             :: "l"(genp), "r"(target) : "memory");
            }
        }

        // overlap: prefetch xg0 for t0 = s+1 while the barrier completes
        if (tid < 96 && s + 1 < TSEQ) {
            const float* p = xg_base + (long)(s + 1) * NBATCH * G3;
            xv0 = ((const float4*)p)[0];
            xv1 = ((const float4*)p)[1];
        }

        // detect: tid0 acquire-polls own bgrp gen, block barrier fans out
        if (tid == 0) {
            unsigned v;
            do {
                asm volatile("ld.acquire.gpu.global.u32 %0, [%1];"
                             : "=r"(v) : "l"(genp));
            } while ((int)(v - target) < 0);
        }
        __syncthreads();
    }
}

// ---------------- dense head: out = tanh(tanh(c1) @ W_out + b_out) ----------------
__global__ void __launch_bounds__(512) dense_kernel(
    const float* __restrict__ Wout, const float* __restrict__ bout,
    float* __restrict__ out)
{
    __shared__ float tsh[HID];
    int b = blockIdx.x;
    int j = threadIdx.x;
    tsh[j] = tanhf(g_h1[0][j * NBATCH + b]);   // final h1 (k-major, buf 0)
    __syncthreads();
    float s = bout[j];
#pragma unroll 8
    for (int k = 0; k < HID; ++k)
        s = fmaf(tsh[k], Wout[(long)k * 512 + j], s);
    out[b * 512 + j] = tanhf(s);
}

// ---------------- launch ----------------
extern "C" void kernel_launch(void* const* d_in, const int* in_sizes, int n_in,
                              void* d_out, int out_size)
{
    const float* x     = (const float*)d_in[0];
    const float* W_i0  = (const float*)d_in[1];
    const float* b_i0  = (const float*)d_in[2];
    const float* W_h0  = (const float*)d_in[3];
    const float* b_hn0 = (const float*)d_in[4];
    const float* W_i1  = (const float*)d_in[5];
    const float* b_i1  = (const float*)d_in[6];
    const float* W_h1  = (const float*)d_in[7];
    const float* b_hn1 = (const float*)d_in[8];
    const float* W_out = (const float*)d_in[9];
    const float* b_out = (const float*)d_in[10];

    float* out = (float*)d_out;
    float* c0  = out + 64 * 512;
    float* c1  = out + 2 * 64 * 512;

    size_t fused_smem = (size_t)(3 * 512 * 24 + 12 * SL + 32 * 25) * sizeof(float);
    cudaFuncSetAttribute(gru_fused_kernel,
                         cudaFuncAttributeMaxDynamicSharedMemorySize, (int)fused_smem);

    dim3 pgrid(G3 / 64, MROWS / 128);

    // layer-0 input projection (bulk)
    proj_kernel<<<pgrid, 256>>>(x, W_i0, b_i0, INFEAT, (long)1024 * 256, (long)256);
    // fused: rec0 + (proj1+rec1 merged), one barrier per step, depth-1 pipeline
    gru_fused_kernel<<<NCTA, NTH, fused_smem>>>(W_h0, b_hn0, W_i1, b_i1,
                                                W_h1, b_hn1, c0, c1);
    // head
    dense_kernel<<<64, 512>>>(W_out, b_out, out);
}

// round 16
// speedup vs baseline: 1.5991x; 1.5991x over previous
#include <cuda_runtime.h>
#include <math.h>

#define TSEQ   1024
#define NSTEP  (TSEQ + 1)
#define NBATCH 64
#define HID    512
#define G3     1536
#define INFEAT 256
#define MROWS  (TSEQ * NBATCH)   // 65536
#define NCTA   128
#define NTH    384
#define SL     (32 * 26)         // one warp-slice of the reduction buffer

// packed f32x2 FMA
#define FMA2(d, a, b, c) \
    asm("fma.rn.f32x2 %0, %1, %2, %3;" : "=l"(d) : "l"(a), "l"(b), "l"(c))

__device__ __forceinline__ float2 u2f2(unsigned long long u) {
    float2 f;
    asm("mov.b64 {%0, %1}, %2;" : "=f"(f.x), "=f"(f.y) : "l"(u));
    return f;
}

// ---------------- scratch (device globals; no allocation) ----------------
__device__ float g_xg[(size_t)MROWS * G3];    // layer0 gate preacts (proj0)
__device__ float g_h0[3][HID * NBATCH];       // layer0 h ring (k-major); [2]=zero
__device__ float g_h1[3][HID * NBATCH];       // layer1 h ring; [2]=zero
__device__ float g_y0r[2][HID * NBATCH];      // y0 ring (k-major)
__device__ unsigned g_cntB[2 * 32];           // per-bgrp barrier count (ret 0)
__device__ unsigned g_genB[2 * 32];           // per-bgrp generation (monotonic)

// ---------------- input projection GEMM (layer 0 only) ----------------
__global__ void __launch_bounds__(256) proj_kernel(
    const float* __restrict__ A, const float* __restrict__ W,
    const float* __restrict__ bias, int K, long sB, long sT)
{
    const int N = G3;
    __shared__ __align__(16) float As2[16][260];
    __shared__ __align__(16) float Bs[16][64];

    int tid  = threadIdx.x;
    int row0 = blockIdx.y * 128;
    int col0 = blockIdx.x * 64;
    int tx = tid & 15, ty = tid >> 4;

    int ar  = row0 + (tid >> 1);
    const float* arow = A + (long)(ar & 63) * sB + (long)(ar >> 6) * sT;
    int akc = (tid & 1) * 8;
    int r2  = (tid >> 1) * 2;

    int bkr = tid >> 4;
    int bc  = (tid & 15) * 4;
    const float* bptr = W + (long)bkr * N + col0 + bc;

    unsigned long long acc[8][2];
#pragma unroll
    for (int i = 0; i < 8; ++i) { acc[i][0] = 0ull; acc[i][1] = 0ull; }

    for (int k0 = 0; k0 < K; k0 += 16) {
        float4 a0 = *(const float4*)(arow + k0 + akc);
        float4 a1 = *(const float4*)(arow + k0 + akc + 4);
        float4 bb = *(const float4*)(bptr + (long)k0 * N);

        *(float2*)&As2[akc + 0][r2] = make_float2(a0.x, a0.x);
        *(float2*)&As2[akc + 1][r2] = make_float2(a0.y, a0.y);
        *(float2*)&As2[akc + 2][r2] = make_float2(a0.z, a0.z);
        *(float2*)&As2[akc + 3][r2] = make_float2(a0.w, a0.w);
        *(float2*)&As2[akc + 4][r2] = make_float2(a1.x, a1.x);
        *(float2*)&As2[akc + 5][r2] = make_float2(a1.y, a1.y);
        *(float2*)&As2[akc + 6][r2] = make_float2(a1.z, a1.z);
        *(float2*)&As2[akc + 7][r2] = make_float2(a1.w, a1.w);
        *(float4*)&Bs[bkr][bc] = bb;
        __syncthreads();

#pragma unroll
        for (int kk = 0; kk < 16; ++kk) {
            ulonglong2 b01 = *(const ulonglong2*)&Bs[kk][tx * 4];
            ulonglong2 a01 = *(const ulonglong2*)&As2[kk][ty * 16];
            ulonglong2 a23 = *(const ulonglong2*)&As2[kk][ty * 16 + 4];
            ulonglong2 a45 = *(const ulonglong2*)&As2[kk][ty * 16 + 8];
            ulonglong2 a67 = *(const ulonglong2*)&As2[kk][ty * 16 + 12];
            unsigned long long ad[8] = {a01.x, a01.y, a23.x, a23.y,
                                        a45.x, a45.y, a67.x, a67.y};
#pragma unroll
            for (int i = 0; i < 8; ++i) {
                FMA2(acc[i][0], ad[i], b01.x, acc[i][0]);
                FMA2(acc[i][1], ad[i], b01.y, acc[i][1]);
            }
        }
        __syncthreads();
    }

    float4 bia = *(const float4*)(bias + col0 + tx * 4);
#pragma unroll
    for (int i = 0; i < 8; ++i) {
        long m = row0 + ty * 8 + i;
        float2 f01 = u2f2(acc[i][0]);
        float2 f23 = u2f2(acc[i][1]);
        float4 v;
        v.x = f01.x + bia.x;
        v.y = f01.y + bia.y;
        v.z = f23.x + bia.z;
        v.w = f23.y + bia.w;
        *(float4*)(g_xg + m * G3 + col0 + tx * 4) = v;
    }
}

// ---------------- per-task GEMM body (one warp: 128 k, 24 gate cols) -------
// src: k-major [512][64] global; wsl: SMEM [512][24]; redsl: [4][32][26]
__device__ __forceinline__ void task_gemm(
    const float* __restrict__ src, const float* __restrict__ wsl,
    float* __restrict__ redsl, int wt, int lane, int b0)
{
    unsigned long long acc[12];
#pragma unroll
    for (int j = 0; j < 12; ++j) acc[j] = 0ull;
    int kbase = wt << 7;                      // 128 k per warp
    const float* hp = src + kbase * NBATCH + b0 + lane;
    const ulonglong2* wp = (const ulonglong2*)(wsl + kbase * 24);
#pragma unroll 8
    for (int kk = 0; kk < 128; ++kk) {
        float hv = __ldcg(hp); hp += NBATCH;
        unsigned long long hd;
        asm("mov.b64 %0, {%1, %1};" : "=l"(hd) : "r"(__float_as_int(hv)));
        ulonglong2 w0 = wp[0], w1 = wp[1], w2 = wp[2];
        FMA2(acc[0],  hd, w0.x, acc[0]);
        FMA2(acc[1],  hd, w0.y, acc[1]);
        FMA2(acc[2],  hd, w1.x, acc[2]);
        FMA2(acc[3],  hd, w1.y, acc[3]);
        FMA2(acc[4],  hd, w2.x, acc[4]);
        FMA2(acc[5],  hd, w2.y, acc[5]);
        ulonglong2 w3 = wp[3], w4 = wp[4], w5 = wp[5];
        FMA2(acc[6],  hd, w3.x, acc[6]);
        FMA2(acc[7],  hd, w3.y, acc[7]);
        FMA2(acc[8],  hd, w4.x, acc[8]);
        FMA2(acc[9],  hd, w4.y, acc[9]);
        FMA2(acc[10], hd, w5.x, acc[10]);
        FMA2(acc[11], hd, w5.y, acc[11]);
        wp += 6;   // row stride = 24 floats = 6 ulonglong2
    }
    unsigned long long* rp =
        (unsigned long long*)(redsl + (wt * 32 + lane) * 26);
#pragma unroll
    for (int j = 0; j < 12; ++j) rp[j] = acc[j];
}

// ---------------- fused persistent pipeline (TX merged into T1) ------------
// 128 CTAs x 384 threads. CTA (bgrp, colgrp): batch [bgrp*32,+32), hidden
// cols [colgrp*8,+8). Step s: warps 0-3 T0 GEMM (t0=s), warps 4-7 T1 h-side
// (h1(t1-1)@Wh1), warps 8-11 T1 y-side (y0(t1)@Wi1), t1=s-1. Gate phase:
// group0 -> T0 (2 elems/thread), groups 1+2 split T1 (1 elem/thread).
__global__ void __launch_bounds__(NTH, 1) gru_fused_kernel(
    const float* __restrict__ Wh0, const float* __restrict__ bhn0,
    const float* __restrict__ Wi1, const float* __restrict__ bi1,
    const float* __restrict__ Wh1, const float* __restrict__ bhn1,
    float* __restrict__ c0out, float* __restrict__ c1out)
{
    const int NG = 24;
    extern __shared__ __align__(16) float sh[];
    float* ws0 = sh;                  // [512][24] W_h0 slice
    float* wsi = ws0 + 512 * NG;      // [512][24] W_i1 slice
    float* ws1 = wsi + 512 * NG;      // [512][24] W_h1 slice
    float* red = ws1 + 512 * NG;      // [12][32][26]: 0-3 T0, 4-7 T1h, 8-11 T1y
    float* xgs = red + 12 * SL;       // [32][25]

    int tid  = threadIdx.x;
    int warp = tid >> 5, lane = tid & 31;
    int cta  = blockIdx.x;
    int bgrp = cta & 1;
    int hc0  = (cta >> 1) * 8;
    int b0   = bgrp * 32;

    unsigned* cntp = &g_cntB[bgrp * 32];
    unsigned* genp = &g_genB[bgrp * 32];

    // load the three weight slices (once); gate col gc for slice col j
    for (int f = tid; f < 512 * NG; f += NTH) {
        int k = f / NG, j = f - k * NG;
        int gc = (j >> 3) * HID + hc0 + (j & 7);
        ws0[f] = Wh0[(long)k * G3 + gc];
        wsi[f] = Wi1[(long)k * G3 + gc];
        ws1[f] = Wh1[(long)k * G3 + gc];
    }

    unsigned base = *((volatile unsigned*)genp);

    // gate-phase mapping
    int gt  = tid >> 7;               // 0: T0; 1: T1 cols 0-3; 2: T1 cols 4-7
    int gi  = tid & 127;
    int eb  = gi & 31;
    int ecq = gi >> 5;                // 0..3
    // T0 (gt 0): elements (eb, ecq) and (eb, ecq+4)
    int ec0 = ecq, ec1 = ecq + 4;
    int ehc0 = hc0 + ec0, ehc1 = hc0 + ec1;
    // T1 (gt 1/2): single element (eb, ecT)
    int ecT  = (gt == 2) ? ecq + 4 : ecq;
    int ehcT = hc0 + ecT;

    // per-group gate constants
    float cA0 = 0.f, cA1 = 0.f;                 // T0: bhn0 for ec0/ec1
    float cAT = 0.f, brT = 0.f, bzT = 0.f, bnT = 0.f;   // T1: col ecT
    if (gt == 0) { cA0 = bhn0[ehc0]; cA1 = bhn0[ehc1]; }
    else {
        cAT = bhn1[ehcT];
        brT = bi1[ehcT];
        bzT = bi1[512 + ehcT];
        bnT = bi1[1024 + ehcT];
    }

    // xg0 prefetch registers (warps 0-2: gate group = warp, b = lane)
    float4 xv0, xv1;
    const float* xg_base = 0;
    if (tid < 96) {
        int b = tid & 31, gg = tid >> 5;
        xg_base = g_xg + (long)(b0 + b) * G3 + gg * HID + hc0;
        xv0 = ((const float4*)xg_base)[0];   // t0 = 0
        xv1 = ((const float4*)xg_base)[1];
    }

    for (int s = 0; s < NSTEP; ++s) {
        int t1 = s - 1;
        bool doT0 = (s < TSEQ);
        bool doT1 = (s >= 1);

        const float* hbuf0 = (s == 0) ? g_h0[2] : g_h0[s & 1];
        const float* hbuf1 = (t1 == 0) ? g_h1[2] : g_h1[t1 & 1];

        // hoisted gate-operand loads (latency hidden under GEMM phase)
        float hp00 = 0.f, hp01 = 0.f, hpT = 0.f;
        if (gt == 0 && doT0) {
            hp00 = __ldcg(&hbuf0[ehc0 * NBATCH + b0 + eb]);
            hp01 = __ldcg(&hbuf0[ehc1 * NBATCH + b0 + eb]);
        }
        if (gt != 0 && doT1) {
            hpT = __ldcg(&hbuf1[ehcT * NBATCH + b0 + eb]);
        }

        // stage prefetched xg0 tile (read in gate phase, after the sync)
        if (tid < 96) {
            int b = tid & 31, gg = tid >> 5;
            float* q = xgs + b * 25 + gg * 8;
            q[0] = xv0.x; q[1] = xv0.y; q[2] = xv0.z; q[3] = xv0.w;
            q[4] = xv1.x; q[5] = xv1.y; q[6] = xv1.z; q[7] = xv1.w;
        }

        // ======== GEMM phase: three warp groups, fully concurrent ========
        if (warp < 4)      { if (doT0) task_gemm(hbuf0, ws0, red,          warp,     lane, b0); }
        else if (warp < 8) { if (doT1) task_gemm(hbuf1, ws1, red + 4 * SL, warp - 4, lane, b0); }
        else               { if (doT1) task_gemm(g_y0r[t1 & 1], wsi, red + 8 * SL, warp - 8, lane, b0); }
        __syncthreads();

        // ======== gate phase ========
        if (gt == 0 && doT0) {
            float hr0 = 0.f, hz0 = 0.f, hn0 = 0.f;
            float hr1 = 0.f, hz1 = 0.f, hn1 = 0.f;
#pragma unroll
            for (int w = 0; w < 4; ++w) {
                const float* pr = red + (w * 32 + eb) * 26;
                hr0 += pr[ec0];      hr1 += pr[ec1];
                hz0 += pr[8 + ec0];  hz1 += pr[8 + ec1];
                hn0 += pr[16 + ec0]; hn1 += pr[16 + ec1];
            }
            float xr0 = xgs[eb * 25 + ec0],      xr1v = xgs[eb * 25 + ec1];
            float xz0 = xgs[eb * 25 + 8 + ec0],  xz1v = xgs[eb * 25 + 8 + ec1];
            float xn0 = xgs[eb * 25 + 16 + ec0], xn1v = xgs[eb * 25 + 16 + ec1];

            float rg0 = 1.f / (1.f + __expf(-(xr0 + hr0)));
            float zg0 = 1.f / (1.f + __expf(-(xz0 + hz0)));
            float ng0 = tanhf(xn0 + rg0 * (hn0 + cA0));
            float hnew0 = (1.f - zg0) * ng0 + zg0 * hp00;
            float rg1 = 1.f / (1.f + __expf(-(xr1v + hr1)));
            float zg1 = 1.f / (1.f + __expf(-(xz1v + hz1)));
            float ng1 = tanhf(xn1v + rg1 * (hn1 + cA1));
            float hnew1 = (1.f - zg1) * ng1 + zg1 * hp01;

            int nb = (s & 1) ^ 1;
            g_h0[nb][ehc0 * NBATCH + b0 + eb] = hnew0;
            g_h0[nb][ehc1 * NBATCH + b0 + eb] = hnew1;
            g_y0r[s & 1][ehc0 * NBATCH + b0 + eb] = tanhf(hnew0);
            g_y0r[s & 1][ehc1 * NBATCH + b0 + eb] = tanhf(hnew1);
            if (s == TSEQ - 1) {
                c0out[(b0 + eb) * HID + ehc0] = hnew0;
                c0out[(b0 + eb) * HID + ehc1] = hnew1;
            }
        }

        if (gt != 0 && doT1) {
            // h-side (slices 4-7) and y-side (slices 8-11), one element
            float hr = 0.f, hz = 0.f, hn = 0.f;
            float yr = 0.f, yz = 0.f, yn = 0.f;
#pragma unroll
            for (int w = 0; w < 4; ++w) {
                const float* ph = red + 4 * SL + (w * 32 + eb) * 26;
                const float* py = red + 8 * SL + (w * 32 + eb) * 26;
                hr += ph[ecT];
                hz += ph[8 + ecT];
                hn += ph[16 + ecT];
                yr += py[ecT];
                yz += py[8 + ecT];
                yn += py[16 + ecT];
            }
            float xr = yr + brT, xz = yz + bzT, xn = yn + bnT;

            float rg = 1.f / (1.f + __expf(-(xr + hr)));
            float zg = 1.f / (1.f + __expf(-(xz + hz)));
            float ng = tanhf(xn + rg * (hn + cAT));
            float hnew = (1.f - zg) * ng + zg * hpT;

            int nb = (t1 & 1) ^ 1;
            g_h1[nb][ehcT * NBATCH + b0 + eb] = hnew;
            if (t1 == TSEQ - 1)
                c1out[(b0 + eb) * HID + ehcT] = hnew;
        }

        __syncthreads();   // all CTA writes issued before tid0's release

        unsigned target = base + (unsigned)s + 1u;

        // arrive: per-bgrp flat release-atomic (64 arrivals)
        if (tid == 0) {
            unsigned old;
            asm volatile("atom.release.gpu.global.add.u32 %0, [%1], %2;"
                         : "=r"(old) : "l"(cntp), "r"(1u) : "memory");
            if (old == 63u) {
                asm volatile("st.global.u32 [%0], %1;"
                             :: "l"(cntp), "r"(0u) : "memory");
                asm volatile("st.release.gpu.global.u32 [%0], %1;"
                             :: "l"(genp), "r"(target) : "memory");
            }
        }

        // overlap: prefetch xg0 for t0 = s+1 while the barrier completes
        if (tid < 96 && s + 1 < TSEQ) {
            const float* p = xg_base + (long)(s + 1) * NBATCH * G3;
            xv0 = ((const float4*)p)[0];
            xv1 = ((const float4*)p)[1];
        }

        // detect: tid0 acquire-polls own bgrp gen, block barrier fans out
        if (tid == 0) {
            unsigned v;
            do {
                asm volatile("ld.acquire.gpu.global.u32 %0, [%1];"
                             : "=r"(v) : "l"(genp));
            } while ((int)(v - target) < 0);
        }
        __syncthreads();
    }
}

// ---------------- dense head: out = tanh(tanh(c1) @ W_out + b_out) ----------------
__global__ void __launch_bounds__(512) dense_kernel(
    const float* __restrict__ Wout, const float* __restrict__ bout,
    float* __restrict__ out)
{
    __shared__ float tsh[HID];
    int b = blockIdx.x;
    int j = threadIdx.x;
    tsh[j] = tanhf(g_h1[0][j * NBATCH + b]);   // final h1 (k-major, buf 0)
    __syncthreads();
    float s = bout[j];
#pragma unroll 8
    for (int k = 0; k < HID; ++k)
        s = fmaf(tsh[k], Wout[(long)k * 512 + j], s);
    out[b * 512 + j] = tanhf(s);
}

// ---------------- launch ----------------
extern "C" void kernel_launch(void* const* d_in, const int* in_sizes, int n_in,
                              void* d_out, int out_size)
{
    const float* x     = (const float*)d_in[0];
    const float* W_i0  = (const float*)d_in[1];
    const float* b_i0  = (const float*)d_in[2];
    const float* W_h0  = (const float*)d_in[3];
    const float* b_hn0 = (const float*)d_in[4];
    const float* W_i1  = (const float*)d_in[5];
    const float* b_i1  = (const float*)d_in[6];
    const float* W_h1  = (const float*)d_in[7];
    const float* b_hn1 = (const float*)d_in[8];
    const float* W_out = (const float*)d_in[9];
    const float* b_out = (const float*)d_in[10];

    float* out = (float*)d_out;
    float* c0  = out + 64 * 512;
    float* c1  = out + 2 * 64 * 512;

    size_t fused_smem = (size_t)(3 * 512 * 24 + 12 * SL + 32 * 25) * sizeof(float);
    cudaFuncSetAttribute(gru_fused_kernel,
                         cudaFuncAttributeMaxDynamicSharedMemorySize, (int)fused_smem);

    dim3 pgrid(G3 / 64, MROWS / 128);

    // layer-0 input projection (bulk)
    proj_kernel<<<pgrid, 256>>>(x, W_i0, b_i0, INFEAT, (long)1024 * 256, (long)256);
    // fused: rec0 + (proj1+rec1 merged), one barrier per step, depth-1 pipeline
    gru_fused_kernel<<<NCTA, NTH, fused_smem>>>(W_h0, b_hn0, W_i1, b_i1,
                                                W_h1, b_hn1, c0, c1);
    // head
    dense_kernel<<<64, 512>>>(W_out, b_out, out);
}

// round 17
// speedup vs baseline: 2.0072x; 1.2552x over previous
#include <cuda_runtime.h>
#include <math.h>

#define TSEQ   1024
#define NSTEP  (TSEQ + 1)
#define NBATCH 64
#define HID    512
#define G3     1536
#define INFEAT 256
#define MROWS  (TSEQ * NBATCH)   // 65536
#define NCTA   128
#define NTH    384
#define SLT    (4 * 32 * 26)     // one task's reduction slice (floats) = 3328

// packed f32x2 FMA
#define FMA2(d, a, b, c) \
    asm("fma.rn.f32x2 %0, %1, %2, %3;" : "=l"(d) : "l"(a), "l"(b), "l"(c))

__device__ __forceinline__ float2 u2f2(unsigned long long u) {
    float2 f;
    asm("mov.b64 {%0, %1}, %2;" : "=f"(f.x), "=f"(f.y) : "l"(u));
    return f;
}

// ---------------- scratch (device globals; no allocation) ----------------
__device__ float g_xg[(size_t)MROWS * G3];    // layer0 gate preacts (proj0)
__device__ float g_h0[3][HID * NBATCH];       // layer0 h ring [col][b]; [2]=zero
__device__ float g_h1[3][HID * NBATCH];       // layer1 h ring; [2]=zero
__device__ float g_y0r[2][HID * NBATCH];      // y0 ring [col][b]
__device__ unsigned g_cnt;                    // barrier count (returns to 0)
__device__ unsigned g_gen;                    // generation (monotonic)

// ---------------- input projection GEMM (layer 0 only) ----------------
__global__ void __launch_bounds__(256) proj_kernel(
    const float* __restrict__ A, const float* __restrict__ W,
    const float* __restrict__ bias, int K, long sB, long sT)
{
    const int N = G3;
    __shared__ __align__(16) float As2[16][260];
    __shared__ __align__(16) float Bs[16][64];

    int tid  = threadIdx.x;
    int row0 = blockIdx.y * 128;
    int col0 = blockIdx.x * 64;
    int tx = tid & 15, ty = tid >> 4;

    int ar  = row0 + (tid >> 1);
    const float* arow = A + (long)(ar & 63) * sB + (long)(ar >> 6) * sT;
    int akc = (tid & 1) * 8;
    int r2  = (tid >> 1) * 2;

    int bkr = tid >> 4;
    int bc  = (tid & 15) * 4;
    const float* bptr = W + (long)bkr * N + col0 + bc;

    unsigned long long acc[8][2];
#pragma unroll
    for (int i = 0; i < 8; ++i) { acc[i][0] = 0ull; acc[i][1] = 0ull; }

    for (int k0 = 0; k0 < K; k0 += 16) {
        float4 a0 = *(const float4*)(arow + k0 + akc);
        float4 a1 = *(const float4*)(arow + k0 + akc + 4);
        float4 bb = *(const float4*)(bptr + (long)k0 * N);

        *(float2*)&As2[akc + 0][r2] = make_float2(a0.x, a0.x);
        *(float2*)&As2[akc + 1][r2] = make_float2(a0.y, a0.y);
        *(float2*)&As2[akc + 2][r2] = make_float2(a0.z, a0.z);
        *(float2*)&As2[akc + 3][r2] = make_float2(a0.w, a0.w);
        *(float2*)&As2[akc + 4][r2] = make_float2(a1.x, a1.x);
        *(float2*)&As2[akc + 5][r2] = make_float2(a1.y, a1.y);
        *(float2*)&As2[akc + 6][r2] = make_float2(a1.z, a1.z);
        *(float2*)&As2[akc + 7][r2] = make_float2(a1.w, a1.w);
        *(float4*)&Bs[bkr][bc] = bb;
        __syncthreads();

#pragma unroll
        for (int kk = 0; kk < 16; ++kk) {
            ulonglong2 b01 = *(const ulonglong2*)&Bs[kk][tx * 4];
            ulonglong2 a01 = *(const ulonglong2*)&As2[kk][ty * 16];
            ulonglong2 a23 = *(const ulonglong2*)&As2[kk][ty * 16 + 4];
            ulonglong2 a45 = *(const ulonglong2*)&As2[kk][ty * 16 + 8];
            ulonglong2 a67 = *(const ulonglong2*)&As2[kk][ty * 16 + 12];
            unsigned long long ad[8] = {a01.x, a01.y, a23.x, a23.y,
                                        a45.x, a45.y, a67.x, a67.y};
#pragma unroll
            for (int i = 0; i < 8; ++i) {
                FMA2(acc[i][0], ad[i], b01.x, acc[i][0]);
                FMA2(acc[i][1], ad[i], b01.y, acc[i][1]);
            }
        }
        __syncthreads();
    }

    float4 bia = *(const float4*)(bias + col0 + tx * 4);
#pragma unroll
    for (int i = 0; i < 8; ++i) {
        long m = row0 + ty * 8 + i;
        float2 f01 = u2f2(acc[i][0]);
        float2 f23 = u2f2(acc[i][1]);
        float4 v;
        v.x = f01.x + bia.x;
        v.y = f01.y + bia.y;
        v.z = f23.x + bia.z;
        v.w = f23.y + bia.w;
        *(float4*)(g_xg + m * G3 + col0 + tx * 4) = v;
    }
}

// ---------------- per-task GEMM body ---------------------------------------
// One warp: 128 k, 12 j-cols, 64 b. src: [512][64] global. wsl: SMEM [512][12].
// Lane l covers b0=2l, b1=2l+1 via one LDG.64 per k. 3 LDS.128 per k (12 w).
// acc[p]   = {D[b0,2p], D[b0,2p+1]}  p=0..5
// acc[6+p] = {D[b1,2p], D[b1,2p+1]}
// redsl float layout: [(wt*32+l)*26 + sub*12 + j], sub=b&1, j=0..11.
__device__ __forceinline__ void task_gemm(
    const float* __restrict__ src, const float* __restrict__ wsl,
    float* __restrict__ redsl, int wt, int lane)
{
    unsigned long long acc[12];
#pragma unroll
    for (int j = 0; j < 12; ++j) acc[j] = 0ull;
    int kbase = wt << 7;                      // 128 k per warp
    const float2* hp = (const float2*)(src + kbase * NBATCH) + lane;
    const ulonglong2* wp = (const ulonglong2*)(wsl + kbase * 12);
#pragma unroll 8
    for (int kk = 0; kk < 128; ++kk) {
        float2 hv = __ldcg(hp); hp += 32;     // next k row (64 floats)
        unsigned long long hd0, hd1;
        asm("mov.b64 %0, {%1, %1};" : "=l"(hd0) : "r"(__float_as_int(hv.x)));
        asm("mov.b64 %0, {%1, %1};" : "=l"(hd1) : "r"(__float_as_int(hv.y)));
        ulonglong2 wa = wp[0], wb = wp[1], wc = wp[2];   // 6 w-pairs
        FMA2(acc[0],  hd0, wa.x, acc[0]);
        FMA2(acc[1],  hd0, wa.y, acc[1]);
        FMA2(acc[2],  hd0, wb.x, acc[2]);
        FMA2(acc[3],  hd0, wb.y, acc[3]);
        FMA2(acc[4],  hd0, wc.x, acc[4]);
        FMA2(acc[5],  hd0, wc.y, acc[5]);
        FMA2(acc[6],  hd1, wa.x, acc[6]);
        FMA2(acc[7],  hd1, wa.y, acc[7]);
        FMA2(acc[8],  hd1, wb.x, acc[8]);
        FMA2(acc[9],  hd1, wb.y, acc[9]);
        FMA2(acc[10], hd1, wc.x, acc[10]);
        FMA2(acc[11], hd1, wc.y, acc[11]);
        wp += 3;   // row stride = 12 floats = 3 ulonglong2
    }
    unsigned long long* rp =
        (unsigned long long*)(redsl + (wt * 32 + lane) * 26);
#pragma unroll
    for (int j = 0; j < 12; ++j) rp[j] = acc[j];
}

// ---------------- fused persistent pipeline (full-batch CTAs) --------------
// 128 CTAs x 384 threads. CTA owns 4 hidden cols (hc0 = cta*4), full batch 64.
// Step s: warps 0-3 T0 (h0(s)@Wh0, t0=s), warps 4-7 T1h (h1(t1-1)@Wh1),
// warps 8-11 T1y (y0(t1)@Wi1), t1=s-1. j = gate*4 + col (12 cols per task).
// One flat 128-arrival grid barrier per step.
__global__ void __launch_bounds__(NTH, 1) gru_fused_kernel(
    const float* __restrict__ Wh0, const float* __restrict__ bhn0,
    const float* __restrict__ Wi1, const float* __restrict__ bi1,
    const float* __restrict__ Wh1, const float* __restrict__ bhn1,
    float* __restrict__ c0out, float* __restrict__ c1out)
{
    extern __shared__ __align__(16) float sh[];
    float* ws0 = sh;                  // [512][12] W_h0 slice
    float* wsi = ws0 + 512 * 12;      // [512][12] W_i1 slice
    float* ws1 = wsi + 512 * 12;      // [512][12] W_h1 slice
    float* red = ws1 + 512 * 12;      // [3][4][32][26]: T0 / T1h / T1y
    float* xgs = red + 3 * SLT;       // [64][17] xg0 staging (stride 17)

    int tid  = threadIdx.x;
    int warp = tid >> 5, lane = tid & 31;
    int cta  = blockIdx.x;
    int hc0  = cta * 4;

    // load the three weight slices (once); j = gate*4 + col
    for (int f = tid; f < 512 * 12; f += NTH) {
        int k = f / 12, j = f - k * 12;
        int gc = (j >> 2) * HID + hc0 + (j & 3);
        ws0[f] = Wh0[(long)k * G3 + gc];
        wsi[f] = Wi1[(long)k * G3 + gc];
        ws1[f] = Wh1[(long)k * G3 + gc];
    }

    unsigned base = *((volatile unsigned*)&g_gen);

    // gate-phase mapping:
    //   gt0 (tid 0..127):   T0, elems (b, cq) and (b+32, cq); b=tid&31, cq=tid>>5
    //   tid 128..383: T1, one elem (b, cq); tid2=tid-128, cq=tid2>>6, b=tid2&63
    int gt   = (tid < 128) ? 0 : 1;
    int cq0  = (tid & 127) >> 5;          // T0 col
    int b0e  = tid & 31;                  // T0 first batch row
    int tid2 = tid - 128;
    int cqT  = (tid2 >> 6) & 3;           // T1 col
    int bT   = tid2 & 63;                 // T1 batch row

    float bhn0_r = 0.f, bhn1_r = 0.f, brT = 0.f, bzT = 0.f, bnT = 0.f;
    if (gt == 0) {
        bhn0_r = bhn0[hc0 + cq0];
    } else {
        bhn1_r = bhn1[hc0 + cqT];
        brT = bi1[hc0 + cqT];
        bzT = bi1[512 + hc0 + cqT];
        bnT = bi1[1024 + hc0 + cqT];
    }

    // xg0 prefetch: thread (gg = tid>>5, l = tid&31) covers (b=l) and (b=l+32),
    // gate gg, cols hc0..hc0+3 (one float4 each)
    float4 xv0, xv1;
    const float* xg_base = 0;
    if (tid < 96) {
        int gg = tid >> 5, l = tid & 31;
        xg_base = g_xg + (long)l * G3 + gg * HID + hc0;
        xv0 = *(const float4*)xg_base;                      // t=0, b=l
        xv1 = *(const float4*)(xg_base + (long)32 * G3);    // t=0, b=l+32
    }

    for (int s = 0; s < NSTEP; ++s) {
        int t1 = s - 1;
        bool doT0 = (s < TSEQ);
        bool doT1 = (s >= 1);

        const float* hbuf0 = (s == 0) ? g_h0[2] : g_h0[s & 1];
        const float* hbuf1 = (t1 == 0) ? g_h1[2] : g_h1[t1 & 1];

        // hoisted gate operands (latency hidden under GEMM phase)
        float hp00 = 0.f, hp01 = 0.f, hpT = 0.f;
        if (gt == 0) {
            if (doT0) {
                hp00 = __ldcg(&hbuf0[(hc0 + cq0) * NBATCH + b0e]);
                hp01 = __ldcg(&hbuf0[(hc0 + cq0) * NBATCH + b0e + 32]);
            }
        } else if (doT1) {
            hpT = __ldcg(&hbuf1[(hc0 + cqT) * NBATCH + bT]);
        }

        // stage prefetched xg0 tile: xgs[b*17 + gg*4 + i]
        if (tid < 96) {
            int gg = tid >> 5, l = tid & 31;
            float* q0 = xgs + l * 17 + gg * 4;
            float* q1 = xgs + (l + 32) * 17 + gg * 4;
            q0[0] = xv0.x; q0[1] = xv0.y; q0[2] = xv0.z; q0[3] = xv0.w;
            q1[0] = xv1.x; q1[1] = xv1.y; q1[2] = xv1.z; q1[3] = xv1.w;
        }

        // ======== GEMM phase: three warp groups, concurrent ========
        if (warp < 4)      { if (doT0) task_gemm(hbuf0, ws0, red,           warp,     lane); }
        else if (warp < 8) { if (doT1) task_gemm(hbuf1, ws1, red + SLT,     warp - 4, lane); }
        else               { if (doT1) task_gemm(g_y0r[t1 & 1], wsi, red + 2 * SLT, warp - 8, lane); }
        __syncthreads();

        // ======== gate phase ========
        if (gt == 0 && doT0) {
            // two elements: (b0e, cq0) and (b0e+32, cq0)
#pragma unroll
            for (int half = 0; half < 2; ++half) {
                int be  = b0e + half * 32;
                int l   = be >> 1, sub = be & 1;
                float hr = 0.f, hz = 0.f, hn = 0.f;
#pragma unroll
                for (int w = 0; w < 4; ++w) {
                    const float* pr = red + (w * 32 + l) * 26 + sub * 12;
                    hr += pr[cq0];
                    hz += pr[4 + cq0];
                    hn += pr[8 + cq0];
                }
                float xr = xgs[be * 17 + cq0];
                float xz = xgs[be * 17 + 4 + cq0];
                float xn = xgs[be * 17 + 8 + cq0];
                float hprev = half ? hp01 : hp00;

                float rg = 1.f / (1.f + __expf(-(xr + hr)));
                float zg = 1.f / (1.f + __expf(-(xz + hz)));
                float ng = tanhf(xn + rg * (hn + bhn0_r));
                float hnew = (1.f - zg) * ng + zg * hprev;

                int nb = (s & 1) ^ 1;
                g_h0[nb][(hc0 + cq0) * NBATCH + be] = hnew;
                g_y0r[s & 1][(hc0 + cq0) * NBATCH + be] = tanhf(hnew);
                if (s == TSEQ - 1)
                    c0out[be * HID + hc0 + cq0] = hnew;
            }
        }

        if (gt == 1 && doT1) {
            int l = bT >> 1, sub = bT & 1;
            float hr = 0.f, hz = 0.f, hn = 0.f;
            float yr = 0.f, yz = 0.f, yn = 0.f;
#pragma unroll
            for (int w = 0; w < 4; ++w) {
                const float* ph = red + SLT     + (w * 32 + l) * 26 + sub * 12;
                const float* py = red + 2 * SLT + (w * 32 + l) * 26 + sub * 12;
                hr += ph[cqT];
                hz += ph[4 + cqT];
                hn += ph[8 + cqT];
                yr += py[cqT];
                yz += py[4 + cqT];
                yn += py[8 + cqT];
            }
            float xr = yr + brT, xz = yz + bzT, xn = yn + bnT;

            float rg = 1.f / (1.f + __expf(-(xr + hr)));
            float zg = 1.f / (1.f + __expf(-(xz + hz)));
            float ng = tanhf(xn + rg * (hn + bhn1_r));
            float hnew = (1.f - zg) * ng + zg * hpT;

            int nb = (t1 & 1) ^ 1;
            g_h1[nb][(hc0 + cqT) * NBATCH + bT] = hnew;
            if (t1 == TSEQ - 1)
                c1out[bT * HID + hc0 + cqT] = hnew;
        }

        __syncthreads();   // all CTA writes issued before tid0's release

        unsigned target = base + (unsigned)s + 1u;

        // arrive: flat release-atomic (128 arrivals; best measured mechanism)
        if (tid == 0) {
            unsigned old;
            asm volatile("atom.release.gpu.global.add.u32 %0, [%1], %2;"
                         : "=r"(old) : "l"(&g_cnt), "r"(1u) : "memory");
            if (old == NCTA - 1u) {
                asm volatile("st.global.u32 [%0], %1;"
                             :: "l"(&g_cnt), "r"(0u) : "memory");
                asm volatile("st.release.gpu.global.u32 [%0], %1;"
                             :: "l"(&g_gen), "r"(target) : "memory");
            }
        }

        // overlap: prefetch xg0 for t0 = s+1 while the barrier completes
        if (tid < 96 && s + 1 < TSEQ) {
            const float* p = xg_base + (long)(s + 1) * NBATCH * G3;
            xv0 = *(const float4*)p;
            xv1 = *(const float4*)(p + (long)32 * G3);
        }

        // detect: tid0 acquire-polls gen, block barrier fans out
        if (tid == 0) {
            unsigned v;
            do {
                asm volatile("ld.acquire.gpu.global.u32 %0, [%1];"
                             : "=r"(v) : "l"(&g_gen));
            } while ((int)(v - target) < 0);
        }
        __syncthreads();
    }
}

// ---------------- dense head: out = tanh(tanh(c1) @ W_out + b_out) ----------------
__global__ void __launch_bounds__(512) dense_kernel(
    const float* __restrict__ Wout, const float* __restrict__ bout,
    float* __restrict__ out)
{
    __shared__ float tsh[HID];
    int b = blockIdx.x;
    int j = threadIdx.x;
    tsh[j] = tanhf(g_h1[0][j * NBATCH + b]);   // final h1 ([col][b], buf 0)
    __syncthreads();
    float s = bout[j];
#pragma unroll 8
    for (int k = 0; k < HID; ++k)
        s = fmaf(tsh[k], Wout[(long)k * 512 + j], s);
    out[b * 512 + j] = tanhf(s);
}

// ---------------- launch ----------------
extern "C" void kernel_launch(void* const* d_in, const int* in_sizes, int n_in,
                              void* d_out, int out_size)
{
    const float* x     = (const float*)d_in[0];
    const float* W_i0  = (const float*)d_in[1];
    const float* b_i0  = (const float*)d_in[2];
    const float* W_h0  = (const float*)d_in[3];
    const float* b_hn0 = (const float*)d_in[4];
    const float* W_i1  = (const float*)d_in[5];
    const float* b_i1  = (const float*)d_in[6];
    const float* W_h1  = (const float*)d_in[7];
    const float* b_hn1 = (const float*)d_in[8];
    const float* W_out = (const float*)d_in[9];
    const float* b_out = (const float*)d_in[10];

    float* out = (float*)d_out;
    float* c0  = out + 64 * 512;
    float* c1  = out + 2 * 64 * 512;

    size_t fused_smem = (size_t)(3 * 512 * 12 + 3 * SLT + 64 * 17) * sizeof(float);
    cudaFuncSetAttribute(gru_fused_kernel,
                         cudaFuncAttributeMaxDynamicSharedMemorySize, (int)fused_smem);

    dim3 pgrid(G3 / 64, MROWS / 128);

    // layer-0 input projection (bulk)
    proj_kernel<<<pgrid, 256>>>(x, W_i0, b_i0, INFEAT, (long)1024 * 256, (long)256);
    // fused: rec0 + (proj1+rec1 merged), full-batch CTAs, halved LDS pressure
    gru_fused_kernel<<<NCTA, NTH, fused_smem>>>(W_h0, b_hn0, W_i1, b_i1,
                                                W_h1, b_hn1, c0, c1);
    // head
    dense_kernel<<<64, 512>>>(W_out, b_out, out);
}